// round 14
// baseline (speedup 1.0000x reference)
#include <cuda_runtime.h>
#include <cuda_bf16.h>
#include <cstdint>

#define NROWS 32768
#define DIM   256
#define NC    8192
#define HM    1e-4f             // score-space margin (= 2e-4 in dist space)
#define CAP   64
#define TCH   4                 // code chunks per CTA
#define GY    (NC / (TCH * 128))   // 16 y-CTAs per row chunk

#define NTHR  256               // 8 warps
#define PITCH 264               // bf16 elems/row smem pitch (256 + pad)
#define SM_A   0                // 128*264*2 = 67584
#define SM_B0  67584
#define SM_B1  135168
#define SMEM_TOTAL 202752       // A + 2 B stages

// ---------------- scratch ----------------------------------------------------
__device__ float g_sumz[NROWS];
__device__ float g_cnorm[NC];
__device__ float g_count[NC];
__device__ float g_wsum[NC * DIM];
__device__ float g_loss;
__device__ float g_n;
__device__ uint32_t g_rmax[NROWS];
__device__ int      g_ccnt[NROWS];
__device__ int      g_cand[NROWS * CAP];
__device__ int      g_done[NROWS / 128];
__device__ __nv_bfloat16 g_zb[NROWS * DIM];
__device__ __nv_bfloat16 g_cb[NC * DIM];

// ---------------- helpers -----------------------------------------------------
__device__ __forceinline__ uint32_t smem_u32(const void* p) {
    uint32_t a;
    asm("{ .reg .u64 t; cvta.to.shared.u64 t, %1; cvt.u32.u64 %0, t; }" : "=r"(a) : "l"(p));
    return a;
}
__device__ __forceinline__ void ldsm4(uint32_t& r0, uint32_t& r1, uint32_t& r2, uint32_t& r3, uint32_t addr) {
    asm volatile("ldmatrix.sync.aligned.m8n8.x4.shared.b16 {%0,%1,%2,%3}, [%4];"
                 : "=r"(r0), "=r"(r1), "=r"(r2), "=r"(r3) : "r"(addr));
}
__device__ __forceinline__ void mma16816(float* c, uint32_t a0, uint32_t a1, uint32_t a2, uint32_t a3,
                                         uint32_t b0, uint32_t b1) {
    asm volatile("mma.sync.aligned.m16n8k16.row.col.f32.bf16.bf16.f32 "
                 "{%0,%1,%2,%3}, {%4,%5,%6,%7}, {%8,%9}, {%0,%1,%2,%3};"
                 : "+f"(c[0]), "+f"(c[1]), "+f"(c[2]), "+f"(c[3])
                 : "r"(a0), "r"(a1), "r"(a2), "r"(a3), "r"(b0), "r"(b1));
}
__device__ __forceinline__ void cpasync16(uint32_t dst, const void* src) {
    asm volatile("cp.async.cg.shared.global [%0], [%1], 16;" :: "r"(dst), "l"(src));
}
// order-preserving float<->uint map (unsigned compare == float compare)
__device__ __forceinline__ uint32_t fmap(float f) {
    uint32_t b = __float_as_uint(f);
    return b ^ (uint32_t)(((int32_t)b >> 31) | 0x80000000);
}
__device__ __forceinline__ float funmap(uint32_t u) {
    uint32_t b = u ^ ((u >> 31) ? 0x80000000u : 0xFFFFFFFFu);
    return __uint_as_float(b);   // funmap(0) = NaN; fmaxf ignores NaN operand
}

// ---------------- zero scratch ------------------------------------------------
__global__ void k_zero() {
    int i = blockIdx.x * blockDim.x + threadIdx.x;
    int stride = gridDim.x * blockDim.x;
    for (int j = i; j < NC * DIM; j += stride) g_wsum[j] = 0.0f;
    for (int j = i; j < NROWS; j += stride) { g_rmax[j] = 0u; g_ccnt[j] = 0; }
    if (i < NROWS / 128) g_done[i] = 0;
    if (i < NC) g_count[i] = 0.0f;
    if (i == 0) { g_loss = 0.0f; g_n = 0.0f; }
}

// ---------------- prep: row norms + bf16 round --------------------------------
__global__ void k_prep(const float* __restrict__ x, __nv_bfloat16* __restrict__ ob,
                       float* __restrict__ norm, int rows) {
    int w = (blockIdx.x * blockDim.x + threadIdx.x) >> 5;
    int lane = threadIdx.x & 31;
    if (w >= rows) return;
    const float* row = x + (size_t)w * DIM;
    float s = 0.0f;
#pragma unroll
    for (int m = 0; m < 8; m++) { float v = row[lane + 32*m]; s = __fadd_rn(s, __fmul_rn(v, v)); }
#pragma unroll
    for (int o = 16; o > 0; o >>= 1) s = __fadd_rn(s, __shfl_down_sync(0xffffffffu, s, o));
    if (lane == 0) norm[w] = s;

    __align__(16) __nv_bfloat16 b0[8];
#pragma unroll
    for (int q = 0; q < 8; q++) b0[q] = __float2bfloat16_rn(row[lane*8 + q]);
    *reinterpret_cast<uint4*>(ob + (size_t)w*DIM + lane*8) = *reinterpret_cast<uint4*>(b0);
}

// ---------------- HMMA GEMM + global candidates + fused last-CTA refine -------
__global__ void __launch_bounds__(NTHR, 1) k_mma(
    const __nv_bfloat16* __restrict__ zb, const __nv_bfloat16* __restrict__ cb,
    const float* __restrict__ zf, const float* __restrict__ cbw,
    const float* __restrict__ sumz, const float* __restrict__ cnorm,
    uint32_t* __restrict__ grmax, int* __restrict__ gccnt, int* __restrict__ gcand,
    int* __restrict__ gdone,
    float* __restrict__ idxf_out, float* __restrict__ zq_out,
    float* __restrict__ wsum, float* __restrict__ cnt, float* __restrict__ lossacc)
{
    extern __shared__ char smem[];
    __nv_bfloat16* As = reinterpret_cast<__nv_bfloat16*>(smem + SM_A);

    const int tid = threadIdx.x;
    const int row0 = blockIdx.x * 128;
    const int colbase = blockIdx.y * (TCH * 128);
    const uint32_t sbA = smem_u32(smem + SM_A);
    const uint32_t sbB[2] = { smem_u32(smem + SM_B0), smem_u32(smem + SM_B1) };

    // prefetch B0 (async), load A (sync)
    {
        const __nv_bfloat16* Bg = cb + (size_t)colbase * DIM;
#pragma unroll
        for (int i = 0; i < 16; i++) {
            int u = tid + i * NTHR;
            int r = u >> 5, ch = u & 31;
            cpasync16(sbB[0] + (uint32_t)((r * PITCH + ch * 8) * 2), Bg + (size_t)r * DIM + ch * 8);
        }
        asm volatile("cp.async.commit_group;");
        const uint4* Ag = reinterpret_cast<const uint4*>(zb + (size_t)row0 * DIM);
#pragma unroll
        for (int i = 0; i < 16; i++) {
            int u = tid + i * NTHR;
            int r = u >> 5, ch = u & 31;
            reinterpret_cast<uint4*>(As + r * PITCH + ch * 8)[0] = Ag[u];
        }
    }

    const int wid = tid >> 5, lane = tid & 31;
    const int wm = wid & 3, wn = wid >> 2;          // 4 x 2 warp grid (32 x 64 tiles)
    const int gq = lane >> 2, t4 = lane & 3;
    const int rl0 = wm*32 + gq;

    const uint32_t aBase = sbA + (uint32_t)(((wm*32 + (lane & 15)) * PITCH + (lane >> 4) * 8) * 2);
    const uint32_t bOff  = (uint32_t)(((wn*64 + (lane & 15)) * PITCH + (lane >> 4) * 8) * 2);

    for (int t = 0; t < TCH; t++) {
        asm volatile("cp.async.wait_group 0;");
        __syncthreads();

        if (t + 1 < TCH) {
            const __nv_bfloat16* Bg = cb + (size_t)(colbase + (t+1)*128) * DIM;
            uint32_t dbase = sbB[(t+1) & 1];
#pragma unroll
            for (int i = 0; i < 16; i++) {
                int u = tid + i * NTHR;
                int r = u >> 5, ch = u & 31;
                cpasync16(dbase + (uint32_t)((r * PITCH + ch * 8) * 2), Bg + (size_t)r * DIM + ch * 8);
            }
            asm volatile("cp.async.commit_group;");
        }

        const uint32_t bBase = sbB[t & 1] + bOff;
        const int col0 = colbase + t*128;

        float acc[2][8][4];
#pragma unroll
        for (int mt = 0; mt < 2; mt++)
#pragma unroll
            for (int nt = 0; nt < 8; nt++)
#pragma unroll
                for (int q = 0; q < 4; q++) acc[mt][nt][q] = 0.0f;

#pragma unroll
        for (int k16 = 0; k16 < 16; k16++) {
            uint32_t a[2][4], b[4][4];
#pragma unroll
            for (int mt = 0; mt < 2; mt++)
                ldsm4(a[mt][0], a[mt][1], a[mt][2], a[mt][3],
                      aBase + (uint32_t)(((mt*16)*PITCH + k16*16) * 2));
#pragma unroll
            for (int ng = 0; ng < 4; ng++)
                ldsm4(b[ng][0], b[ng][1], b[ng][2], b[ng][3],
                      bBase + (uint32_t)(((ng*16)*PITCH + k16*16) * 2));
#pragma unroll
            for (int mt = 0; mt < 2; mt++)
#pragma unroll
                for (int ng = 0; ng < 4; ng++) {
                    mma16816(acc[mt][2*ng+0], a[mt][0], a[mt][1], a[mt][2], a[mt][3], b[ng][0], b[ng][2]);
                    mma16816(acc[mt][2*ng+1], a[mt][0], a[mt][1], a[mt][2], a[mt][3], b[ng][1], b[ng][3]);
                }
        }

        // ---- score-space epilogue with GLOBAL running max ------------------
#pragma unroll
        for (int mt = 0; mt < 2; mt++) {
            float sc[8][4];
            float mx_lo = -3.4e38f, mx_hi = -3.4e38f;
#pragma unroll
            for (int nt = 0; nt < 8; nt++) {
                int col = col0 + wn*64 + nt*8 + t4*2;
                float2 cn = *reinterpret_cast<const float2*>(cnorm + col);
                sc[nt][0] = __fmaf_rn(cn.x, -0.5f, acc[mt][nt][0]);
                sc[nt][1] = __fmaf_rn(cn.y, -0.5f, acc[mt][nt][1]);
                sc[nt][2] = __fmaf_rn(cn.x, -0.5f, acc[mt][nt][2]);
                sc[nt][3] = __fmaf_rn(cn.y, -0.5f, acc[mt][nt][3]);
                mx_lo = fmaxf(mx_lo, fmaxf(sc[nt][0], sc[nt][1]));
                mx_hi = fmaxf(mx_hi, fmaxf(sc[nt][2], sc[nt][3]));
            }
#pragma unroll
            for (int o = 1; o < 4; o <<= 1) {
                mx_lo = fmaxf(mx_lo, __shfl_xor_sync(0xffffffffu, mx_lo, o));
                mx_hi = fmaxf(mx_hi, __shfl_xor_sync(0xffffffffu, mx_hi, o));
            }
            int rlo = row0 + rl0 + mt*16, rhi = rlo + 8;
            uint32_t old_lo = 0u, old_hi = 0u;
            if (t4 == 0) {
                old_lo = atomicMax(&grmax[rlo], fmap(mx_lo));
                old_hi = atomicMax(&grmax[rhi], fmap(mx_hi));
            }
            old_lo = __shfl_sync(0xffffffffu, old_lo, lane & ~3);
            old_hi = __shfl_sync(0xffffffffu, old_hi, lane & ~3);
            float Tlo = fmaxf(mx_lo, funmap(old_lo)) - HM;
            float Thi = fmaxf(mx_hi, funmap(old_hi)) - HM;
#pragma unroll
            for (int nt = 0; nt < 8; nt++) {
                int col = col0 + wn*64 + nt*8 + t4*2;
#pragma unroll
                for (int q = 0; q < 4; q++) {
                    int r    = (q < 2) ? rlo : rhi;
                    float T  = (q < 2) ? Tlo : Thi;
                    if (sc[nt][q] >= T) {
                        int pos = atomicAdd(&gccnt[r], 1);
                        if (pos < CAP) gcand[r*CAP + pos] = col + (q & 1);
                    }
                }
            }
        }
    }

    // ---- last-CTA-per-row-chunk ticket: winner refines + scatters ------------
    __threadfence();                    // release our gcand/gccnt/grmax writes
    __shared__ int s_old;
    __syncthreads();
    if (tid == 0) s_old = atomicAdd(&gdone[blockIdx.x], 1);
    __syncthreads();
    if (s_old != GY - 1) return;
    __threadfence();                    // acquire other CTAs' writes

    // warp `wid` owns rows row0 + wid*16 .. +15
    for (int rr = 0; rr < 16; rr++) {
        int w  = row0 + wid * 16 + rr;
        const float* zr = zf + (size_t)w * DIM;
        float szr = sumz[w];
        float bv = 3.4e38f; int bi = NC;
        int n = gccnt[w];
        if (n <= CAP) {
            for (int i = lane; i < n; i += 32) {
                int cc = gcand[w*CAP + i];
                const float* cr = cbw + (size_t)cc * DIM;
                float acc2 = 0.0f;
                for (int k2 = 0; k2 < DIM; k2++) acc2 = __fmaf_rn(zr[k2], cr[k2], acc2);
                float de = __fadd_rn(__fadd_rn(szr, -2.0f * acc2), cnorm[cc]);
                if (de < bv || (de == bv && cc < bi)) { bv = de; bi = cc; }
            }
        } else {
            for (int cc = lane; cc < NC; cc += 32) {
                const float* cr = cbw + (size_t)cc * DIM;
                float acc2 = 0.0f;
                for (int k2 = 0; k2 < DIM; k2++) acc2 = __fmaf_rn(zr[k2], cr[k2], acc2);
                float de = __fadd_rn(__fadd_rn(szr, -2.0f * acc2), cnorm[cc]);
                if (de < bv || (de == bv && cc < bi)) { bv = de; bi = cc; }
            }
        }
#pragma unroll
        for (int o = 16; o > 0; o >>= 1) {
            float ov = __shfl_xor_sync(0xffffffffu, bv, o);
            int   oi = __shfl_xor_sync(0xffffffffu, bi, o);
            if (ov < bv || (ov == bv && oi < bi)) { bv = ov; bi = oi; }
        }
        if (lane == 0) idxf_out[w] = (float)bi;

        const float* cr = cbw + (size_t)bi * DIM;
        float ls = 0.0f;
#pragma unroll
        for (int m = 0; m < 8; m++) {
            int d = lane + 32*m;
            float zv = zr[d], cv = cr[d];
            atomicAdd(&wsum[bi * DIM + d], zv);
            float diff = __fadd_rn(zv, -cv);
            ls = __fadd_rn(ls, __fmul_rn(diff, diff));
            float st = __fadd_rn(cv, -zv);
            zq_out[(size_t)w * DIM + d] = __fadd_rn(zv, st);
        }
#pragma unroll
        for (int o = 16; o > 0; o >>= 1) ls = __fadd_rn(ls, __shfl_down_sync(0xffffffffu, ls, o));
        if (lane == 0) { atomicAdd(&cnt[bi], 1.0f); atomicAdd(lossacc, ls); }
    }
}

// ---------------- EMA count + n ----------------------------------------------
__global__ void k_ema(const float* __restrict__ ema_count, const float* __restrict__ cntv,
                      float* __restrict__ out_count, float* __restrict__ n_acc) {
    int c = blockIdx.x * blockDim.x + threadIdx.x;
    float nec = 0.0f;
    if (c < NC) {
        nec = __fadd_rn(__fmul_rn(0.99f, ema_count[c]), __fmul_rn(0.01f, cntv[c]));
        out_count[c] = nec;
    }
    __shared__ float red[256];
    red[threadIdx.x] = nec;
    __syncthreads();
    for (int s = 128; s > 0; s >>= 1) {
        if (threadIdx.x < s) red[threadIdx.x] = __fadd_rn(red[threadIdx.x], red[threadIdx.x + s]);
        __syncthreads();
    }
    if (threadIdx.x == 0) atomicAdd(n_acc, red[0]);
}

// ---------------- new codebook + new ema weight -------------------------------
__global__ void k_codebook(const float* __restrict__ ema_weight, const float* __restrict__ wsum,
                           const float* __restrict__ out_count, const float* __restrict__ n_acc,
                           float* __restrict__ out_cb, float* __restrict__ out_ew) {
    size_t i = (size_t)blockIdx.x * 256 + threadIdx.x;
    if (i >= (size_t)NC * DIM) return;
    int c = (int)(i >> 8);
    float new_ew = __fadd_rn(__fmul_rn(0.99f, ema_weight[i]), __fmul_rn(0.01f, wsum[i]));
    out_ew[i] = new_ew;
    float n  = *n_acc;
    float a  = __fadd_rn(out_count[c], 1e-5f);
    float b  = __fadd_rn(n, 0.08192f);
    float cs = __fmul_rn(__fdiv_rn(a, b), n);
    out_cb[i] = __fdiv_rn(new_ew, cs);
}

__global__ void k_loss(const float* __restrict__ lossacc, float* __restrict__ out_loss) {
    float m = __fdiv_rn(*lossacc, 8388608.0f);
    *out_loss = __fmul_rn(0.25f, m);
}

// ---------------- launch ------------------------------------------------------
extern "C" void kernel_launch(void* const* d_in, const int* in_sizes, int n_in,
                              void* d_out, int out_size) {
    const float* z          = (const float*)d_in[0];
    const float* cbw        = (const float*)d_in[1];
    const float* ema_count  = (const float*)d_in[2];
    const float* ema_weight = (const float*)d_in[3];

    float* out      = (float*)d_out;
    float* out_zq   = out;
    float* out_idx  = out + 8388608;
    float* out_loss = out + 8421376;
    float* out_cb   = out + 8421377;
    float* out_cnt  = out + 10518529;
    float* out_ew   = out + 10526721;

    float *p_sumz, *p_cnorm, *p_count, *p_wsum, *p_loss, *p_n;
    uint32_t* p_rmax;
    int *p_ccnt, *p_cand, *p_done;
    __nv_bfloat16 *p_zb, *p_cb;
    cudaGetSymbolAddress((void**)&p_sumz,  g_sumz);
    cudaGetSymbolAddress((void**)&p_cnorm, g_cnorm);
    cudaGetSymbolAddress((void**)&p_count, g_count);
    cudaGetSymbolAddress((void**)&p_wsum,  g_wsum);
    cudaGetSymbolAddress((void**)&p_loss,  g_loss);
    cudaGetSymbolAddress((void**)&p_n,     g_n);
    cudaGetSymbolAddress((void**)&p_rmax,  g_rmax);
    cudaGetSymbolAddress((void**)&p_ccnt,  g_ccnt);
    cudaGetSymbolAddress((void**)&p_cand,  g_cand);
    cudaGetSymbolAddress((void**)&p_done,  g_done);
    cudaGetSymbolAddress((void**)&p_zb,    g_zb);
    cudaGetSymbolAddress((void**)&p_cb,    g_cb);

    cudaFuncSetAttribute(k_mma, cudaFuncAttributeMaxDynamicSharedMemorySize, SMEM_TOTAL);

    k_zero<<<2048, 256>>>();
    k_prep<<<4096, 256>>>(z,   p_zb, p_sumz,  NROWS);
    k_prep<<<1024, 256>>>(cbw, p_cb, p_cnorm, NC);
    dim3 grid(NROWS/128, GY);   // x = row chunk (fastest)
    k_mma<<<grid, NTHR, SMEM_TOTAL>>>(p_zb, p_cb, z, cbw, p_sumz, p_cnorm,
                                      p_rmax, p_ccnt, p_cand, p_done,
                                      out_idx, out_zq, p_wsum, p_count, p_loss);
    k_ema<<<32, 256>>>(ema_count, p_count, out_cnt, p_n);
    k_codebook<<<8192, 256>>>(ema_weight, p_wsum, out_cnt, p_n, out_cb, out_ew);
    k_loss<<<1, 1>>>(p_loss, out_loss);
}

// round 15
// speedup vs baseline: 1.3500x; 1.3500x over previous
#include <cuda_runtime.h>
#include <cuda_bf16.h>
#include <cstdint>

#define NROWS 32768
#define DIM   256
#define NC    8192
#define HM    1e-4f             // score-space margin (= 2e-4 in dist space)
#define CAP   64
#define TCH   4                 // code chunks per CTA

#define NTHR  256               // 8 warps
#define PITCH 264               // bf16 elems/row smem pitch (256 + pad)
#define SM_A   0                // 128*264*2 = 67584
#define SM_B0  67584
#define SM_B1  135168
#define SMEM_TOTAL 202752       // A + 2 B stages

// ---------------- scratch ----------------------------------------------------
__device__ float g_sumz[NROWS];
__device__ float g_cnorm[NC];
__device__ float g_count[NC];
__device__ float g_wsum[NC * DIM];
__device__ float g_loss;
__device__ float g_n;
__device__ uint32_t g_rmax[NROWS];          // order-mapped score max per row
__device__ int      g_ccnt[NROWS];
__device__ int      g_cand[NROWS * CAP];
__device__ __nv_bfloat16 g_zb[NROWS * DIM];
__device__ __nv_bfloat16 g_cb[NC * DIM];

// ---------------- helpers -----------------------------------------------------
__device__ __forceinline__ uint32_t smem_u32(const void* p) {
    uint32_t a;
    asm("{ .reg .u64 t; cvta.to.shared.u64 t, %1; cvt.u32.u64 %0, t; }" : "=r"(a) : "l"(p));
    return a;
}
__device__ __forceinline__ void ldsm4(uint32_t& r0, uint32_t& r1, uint32_t& r2, uint32_t& r3, uint32_t addr) {
    asm volatile("ldmatrix.sync.aligned.m8n8.x4.shared.b16 {%0,%1,%2,%3}, [%4];"
                 : "=r"(r0), "=r"(r1), "=r"(r2), "=r"(r3) : "r"(addr));
}
__device__ __forceinline__ void mma16816(float* c, uint32_t a0, uint32_t a1, uint32_t a2, uint32_t a3,
                                         uint32_t b0, uint32_t b1) {
    asm volatile("mma.sync.aligned.m16n8k16.row.col.f32.bf16.bf16.f32 "
                 "{%0,%1,%2,%3}, {%4,%5,%6,%7}, {%8,%9}, {%0,%1,%2,%3};"
                 : "+f"(c[0]), "+f"(c[1]), "+f"(c[2]), "+f"(c[3])
                 : "r"(a0), "r"(a1), "r"(a2), "r"(a3), "r"(b0), "r"(b1));
}
__device__ __forceinline__ void cpasync16(uint32_t dst, const void* src) {
    asm volatile("cp.async.cg.shared.global [%0], [%1], 16;" :: "r"(dst), "l"(src));
}
// order-preserving float<->uint map (unsigned compare == float compare)
__device__ __forceinline__ uint32_t fmap(float f) {
    uint32_t b = __float_as_uint(f);
    return b ^ (uint32_t)(((int32_t)b >> 31) | 0x80000000);
}
__device__ __forceinline__ float funmap(uint32_t u) {
    uint32_t b = u ^ ((u >> 31) ? 0x80000000u : 0xFFFFFFFFu);
    return __uint_as_float(b);   // funmap(0) = NaN; fmaxf ignores NaN operand
}

// ---------------- zero scratch ------------------------------------------------
__global__ void k_zero() {
    int i = blockIdx.x * blockDim.x + threadIdx.x;
    int stride = gridDim.x * blockDim.x;
    for (int j = i; j < NC * DIM; j += stride) g_wsum[j] = 0.0f;
    for (int j = i; j < NROWS; j += stride) { g_rmax[j] = 0u; g_ccnt[j] = 0; }
    if (i < NC) g_count[i] = 0.0f;
    if (i == 0) { g_loss = 0.0f; g_n = 0.0f; }
}

// ---------------- prep: row norms + bf16 round --------------------------------
__global__ void k_prep(const float* __restrict__ x, __nv_bfloat16* __restrict__ ob,
                       float* __restrict__ norm, int rows) {
    int w = (blockIdx.x * blockDim.x + threadIdx.x) >> 5;
    int lane = threadIdx.x & 31;
    if (w >= rows) return;
    const float* row = x + (size_t)w * DIM;
    float s = 0.0f;
#pragma unroll
    for (int m = 0; m < 8; m++) { float v = row[lane + 32*m]; s = __fadd_rn(s, __fmul_rn(v, v)); }
#pragma unroll
    for (int o = 16; o > 0; o >>= 1) s = __fadd_rn(s, __shfl_down_sync(0xffffffffu, s, o));
    if (lane == 0) norm[w] = s;

    __align__(16) __nv_bfloat16 b0[8];
#pragma unroll
    for (int q = 0; q < 8; q++) b0[q] = __float2bfloat16_rn(row[lane*8 + q]);
    *reinterpret_cast<uint4*>(ob + (size_t)w*DIM + lane*8) = *reinterpret_cast<uint4*>(b0);
}

// ---------------- HMMA GEMM + global online candidate selection ----------------
// grid (256 row-chunks [x fastest], 16 code-quads). A resident; B double-buffered.
__global__ void __launch_bounds__(NTHR, 1) k_mma(
    const __nv_bfloat16* __restrict__ zb, const __nv_bfloat16* __restrict__ cb,
    const float* __restrict__ cnorm,
    uint32_t* __restrict__ grmax, int* __restrict__ gccnt, int* __restrict__ gcand)
{
    extern __shared__ char smem[];
    __nv_bfloat16* As = reinterpret_cast<__nv_bfloat16*>(smem + SM_A);

    const int tid = threadIdx.x;
    const int row0 = blockIdx.x * 128;
    const int colbase = blockIdx.y * (TCH * 128);
    const uint32_t sbA = smem_u32(smem + SM_A);
    const uint32_t sbB[2] = { smem_u32(smem + SM_B0), smem_u32(smem + SM_B1) };

    // prefetch B0 (async), load A (sync) — overlap naturally
    {
        const __nv_bfloat16* Bg = cb + (size_t)colbase * DIM;
#pragma unroll
        for (int i = 0; i < 16; i++) {
            int u = tid + i * NTHR;
            int r = u >> 5, ch = u & 31;
            cpasync16(sbB[0] + (uint32_t)((r * PITCH + ch * 8) * 2), Bg + (size_t)r * DIM + ch * 8);
        }
        asm volatile("cp.async.commit_group;");
        const uint4* Ag = reinterpret_cast<const uint4*>(zb + (size_t)row0 * DIM);
#pragma unroll
        for (int i = 0; i < 16; i++) {
            int u = tid + i * NTHR;
            int r = u >> 5, ch = u & 31;
            reinterpret_cast<uint4*>(As + r * PITCH + ch * 8)[0] = Ag[u];
        }
    }

    const int wid = tid >> 5, lane = tid & 31;
    const int wm = wid & 3, wn = wid >> 2;          // 4 x 2 warp grid (32 x 64 tiles)
    const int gq = lane >> 2, t4 = lane & 3;
    const int rl0 = wm*32 + gq;

    const uint32_t aBase = sbA + (uint32_t)(((wm*32 + (lane & 15)) * PITCH + (lane >> 4) * 8) * 2);
    const uint32_t bOff  = (uint32_t)(((wn*64 + (lane & 15)) * PITCH + (lane >> 4) * 8) * 2);

    for (int t = 0; t < TCH; t++) {
        asm volatile("cp.async.wait_group 0;");
        __syncthreads();   // B(t) visible; all warps done with buffer (t+1)&1

        if (t + 1 < TCH) { // prefetch B(t+1) into the other buffer (hidden by compute)
            const __nv_bfloat16* Bg = cb + (size_t)(colbase + (t+1)*128) * DIM;
            uint32_t dbase = sbB[(t+1) & 1];
#pragma unroll
            for (int i = 0; i < 16; i++) {
                int u = tid + i * NTHR;
                int r = u >> 5, ch = u & 31;
                cpasync16(dbase + (uint32_t)((r * PITCH + ch * 8) * 2), Bg + (size_t)r * DIM + ch * 8);
            }
            asm volatile("cp.async.commit_group;");
        }

        const uint32_t bBase = sbB[t & 1] + bOff;
        const int col0 = colbase + t*128;

        float acc[2][8][4];
#pragma unroll
        for (int mt = 0; mt < 2; mt++)
#pragma unroll
            for (int nt = 0; nt < 8; nt++)
#pragma unroll
                for (int q = 0; q < 4; q++) acc[mt][nt][q] = 0.0f;

        // 16 uninterrupted k-steps: 96 LDSM + 256 MMA per warp
#pragma unroll
        for (int k16 = 0; k16 < 16; k16++) {
            uint32_t a[2][4], b[4][4];
#pragma unroll
            for (int mt = 0; mt < 2; mt++)
                ldsm4(a[mt][0], a[mt][1], a[mt][2], a[mt][3],
                      aBase + (uint32_t)(((mt*16)*PITCH + k16*16) * 2));
#pragma unroll
            for (int ng = 0; ng < 4; ng++)
                ldsm4(b[ng][0], b[ng][1], b[ng][2], b[ng][3],
                      bBase + (uint32_t)(((ng*16)*PITCH + k16*16) * 2));
#pragma unroll
            for (int mt = 0; mt < 2; mt++)
#pragma unroll
                for (int ng = 0; ng < 4; ng++) {
                    mma16816(acc[mt][2*ng+0], a[mt][0], a[mt][1], a[mt][2], a[mt][3], b[ng][0], b[ng][2]);
                    mma16816(acc[mt][2*ng+1], a[mt][0], a[mt][1], a[mt][2], a[mt][3], b[ng][1], b[ng][3]);
                }
        }

        // ---- score-space epilogue with GLOBAL running max ------------------
#pragma unroll
        for (int mt = 0; mt < 2; mt++) {
            float sc[8][4];
            float mx_lo = -3.4e38f, mx_hi = -3.4e38f;
#pragma unroll
            for (int nt = 0; nt < 8; nt++) {
                int col = col0 + wn*64 + nt*8 + t4*2;
                float2 cn = *reinterpret_cast<const float2*>(cnorm + col);
                sc[nt][0] = __fmaf_rn(cn.x, -0.5f, acc[mt][nt][0]);
                sc[nt][1] = __fmaf_rn(cn.y, -0.5f, acc[mt][nt][1]);
                sc[nt][2] = __fmaf_rn(cn.x, -0.5f, acc[mt][nt][2]);
                sc[nt][3] = __fmaf_rn(cn.y, -0.5f, acc[mt][nt][3]);
                mx_lo = fmaxf(mx_lo, fmaxf(sc[nt][0], sc[nt][1]));
                mx_hi = fmaxf(mx_hi, fmaxf(sc[nt][2], sc[nt][3]));
            }
#pragma unroll
            for (int o = 1; o < 4; o <<= 1) {
                mx_lo = fmaxf(mx_lo, __shfl_xor_sync(0xffffffffu, mx_lo, o));
                mx_hi = fmaxf(mx_hi, __shfl_xor_sync(0xffffffffu, mx_hi, o));
            }
            int rlo = row0 + rl0 + mt*16, rhi = rlo + 8;
            uint32_t old_lo = 0u, old_hi = 0u;
            if (t4 == 0) {
                old_lo = atomicMax(&grmax[rlo], fmap(mx_lo));
                old_hi = atomicMax(&grmax[rhi], fmap(mx_hi));
            }
            old_lo = __shfl_sync(0xffffffffu, old_lo, lane & ~3);
            old_hi = __shfl_sync(0xffffffffu, old_hi, lane & ~3);
            float Tlo = fmaxf(mx_lo, funmap(old_lo)) - HM;
            float Thi = fmaxf(mx_hi, funmap(old_hi)) - HM;
#pragma unroll
            for (int nt = 0; nt < 8; nt++) {
                int col = col0 + wn*64 + nt*8 + t4*2;
#pragma unroll
                for (int q = 0; q < 4; q++) {
                    int r    = (q < 2) ? rlo : rhi;
                    float T  = (q < 2) ? Tlo : Thi;
                    if (sc[nt][q] >= T) {
                        int pos = atomicAdd(&gccnt[r], 1);
                        if (pos < CAP) gcand[r*CAP + pos] = col + (q & 1);
                    }
                }
            }
        }
    }
}

// ---------------- warp-cooperative exact refinement + scatter ------------------
// One warp per row. Whole warp computes each candidate's dot: coalesced loads,
// 8 FMA/lane + xor-shuffle reduce (all lanes get the same total).
__global__ void k_refine(const float* __restrict__ zf, const float* __restrict__ cbw,
                         const float* __restrict__ sumz, const float* __restrict__ cnorm,
                         const int* __restrict__ gccnt, const int* __restrict__ gcand,
                         float* __restrict__ idxf_out, float* __restrict__ zq_out,
                         float* __restrict__ wsum, float* __restrict__ cnt,
                         float* __restrict__ lossacc) {
    int w = (blockIdx.x * blockDim.x + threadIdx.x) >> 5;
    int lane = threadIdx.x & 31;
    if (w >= NROWS) return;
    const float* zr = zf + (size_t)w * DIM;
    float szr = sumz[w];

    // preload z row: lane owns dims lane, lane+32, ..., lane+224 (coalesced)
    float zv[8];
#pragma unroll
    for (int m = 0; m < 8; m++) zv[m] = zr[lane + 32*m];

    float bv = 3.4e38f; int bi = NC;
    int n = gccnt[w];
    if (n <= CAP) {
        for (int i = 0; i < n; i++) {
            int cc = gcand[w*CAP + i];                   // broadcast load
            const float* cr = cbw + (size_t)cc * DIM;
            float s = 0.0f;
#pragma unroll
            for (int m = 0; m < 8; m++) s = __fmaf_rn(zv[m], cr[lane + 32*m], s);
#pragma unroll
            for (int o = 16; o > 0; o >>= 1) s = __fadd_rn(s, __shfl_xor_sync(0xffffffffu, s, o));
            float de = __fadd_rn(__fadd_rn(szr, -2.0f * s), cnorm[cc]);
            if (de < bv || (de == bv && cc < bi)) { bv = de; bi = cc; }
        }
        // all lanes already agree on (bv, bi)
    } else {
        // rare fallback: per-lane serial scan over all codes
        for (int cc = lane; cc < NC; cc += 32) {
            const float* cr = cbw + (size_t)cc * DIM;
            float acc2 = 0.0f;
            for (int k2 = 0; k2 < DIM; k2++) acc2 = __fmaf_rn(zr[k2], cr[k2], acc2);
            float de = __fadd_rn(__fadd_rn(szr, -2.0f * acc2), cnorm[cc]);
            if (de < bv || (de == bv && cc < bi)) { bv = de; bi = cc; }
        }
#pragma unroll
        for (int o = 16; o > 0; o >>= 1) {
            float ov = __shfl_xor_sync(0xffffffffu, bv, o);
            int   oi = __shfl_xor_sync(0xffffffffu, bi, o);
            if (ov < bv || (ov == bv && oi < bi)) { bv = ov; bi = oi; }
        }
    }
    if (lane == 0) idxf_out[w] = (float)bi;

    // scatter: wsum atomics, loss partial, straight-through zq
    const float* cr = cbw + (size_t)bi * DIM;
    float ls = 0.0f;
#pragma unroll
    for (int m = 0; m < 8; m++) {
        int d = lane + 32*m;
        float zvv = zv[m], cv = cr[d];
        atomicAdd(&wsum[bi * DIM + d], zvv);
        float diff = __fadd_rn(zvv, -cv);
        ls = __fadd_rn(ls, __fmul_rn(diff, diff));
        float st = __fadd_rn(cv, -zvv);
        zq_out[(size_t)w * DIM + d] = __fadd_rn(zvv, st);
    }
#pragma unroll
    for (int o = 16; o > 0; o >>= 1) ls = __fadd_rn(ls, __shfl_down_sync(0xffffffffu, ls, o));
    if (lane == 0) { atomicAdd(&cnt[bi], 1.0f); atomicAdd(lossacc, ls); }
}

// ---------------- EMA count + n ----------------------------------------------
__global__ void k_ema(const float* __restrict__ ema_count, const float* __restrict__ cntv,
                      float* __restrict__ out_count, float* __restrict__ n_acc) {
    int c = blockIdx.x * blockDim.x + threadIdx.x;
    float nec = 0.0f;
    if (c < NC) {
        nec = __fadd_rn(__fmul_rn(0.99f, ema_count[c]), __fmul_rn(0.01f, cntv[c]));
        out_count[c] = nec;
    }
    __shared__ float red[256];
    red[threadIdx.x] = nec;
    __syncthreads();
    for (int s = 128; s > 0; s >>= 1) {
        if (threadIdx.x < s) red[threadIdx.x] = __fadd_rn(red[threadIdx.x], red[threadIdx.x + s]);
        __syncthreads();
    }
    if (threadIdx.x == 0) atomicAdd(n_acc, red[0]);
}

// ---------------- new codebook + new ema weight -------------------------------
__global__ void k_codebook(const float* __restrict__ ema_weight, const float* __restrict__ wsum,
                           const float* __restrict__ out_count, const float* __restrict__ n_acc,
                           float* __restrict__ out_cb, float* __restrict__ out_ew) {
    size_t i = (size_t)blockIdx.x * 256 + threadIdx.x;
    if (i >= (size_t)NC * DIM) return;
    int c = (int)(i >> 8);
    float new_ew = __fadd_rn(__fmul_rn(0.99f, ema_weight[i]), __fmul_rn(0.01f, wsum[i]));
    out_ew[i] = new_ew;
    float n  = *n_acc;
    float a  = __fadd_rn(out_count[c], 1e-5f);
    float b  = __fadd_rn(n, 0.08192f);
    float cs = __fmul_rn(__fdiv_rn(a, b), n);
    out_cb[i] = __fdiv_rn(new_ew, cs);
}

__global__ void k_loss(const float* __restrict__ lossacc, float* __restrict__ out_loss) {
    float m = __fdiv_rn(*lossacc, 8388608.0f);
    *out_loss = __fmul_rn(0.25f, m);
}

// ---------------- launch ------------------------------------------------------
extern "C" void kernel_launch(void* const* d_in, const int* in_sizes, int n_in,
                              void* d_out, int out_size) {
    const float* z          = (const float*)d_in[0];
    const float* cbw        = (const float*)d_in[1];
    const float* ema_count  = (const float*)d_in[2];
    const float* ema_weight = (const float*)d_in[3];

    float* out      = (float*)d_out;
    float* out_zq   = out;
    float* out_idx  = out + 8388608;
    float* out_loss = out + 8421376;
    float* out_cb   = out + 8421377;
    float* out_cnt  = out + 10518529;
    float* out_ew   = out + 10526721;

    float *p_sumz, *p_cnorm, *p_count, *p_wsum, *p_loss, *p_n;
    uint32_t* p_rmax;
    int *p_ccnt, *p_cand;
    __nv_bfloat16 *p_zb, *p_cb;
    cudaGetSymbolAddress((void**)&p_sumz,  g_sumz);
    cudaGetSymbolAddress((void**)&p_cnorm, g_cnorm);
    cudaGetSymbolAddress((void**)&p_count, g_count);
    cudaGetSymbolAddress((void**)&p_wsum,  g_wsum);
    cudaGetSymbolAddress((void**)&p_loss,  g_loss);
    cudaGetSymbolAddress((void**)&p_n,     g_n);
    cudaGetSymbolAddress((void**)&p_rmax,  g_rmax);
    cudaGetSymbolAddress((void**)&p_ccnt,  g_ccnt);
    cudaGetSymbolAddress((void**)&p_cand,  g_cand);
    cudaGetSymbolAddress((void**)&p_zb,    g_zb);
    cudaGetSymbolAddress((void**)&p_cb,    g_cb);

    cudaFuncSetAttribute(k_mma, cudaFuncAttributeMaxDynamicSharedMemorySize, SMEM_TOTAL);

    k_zero<<<2048, 256>>>();
    k_prep<<<4096, 256>>>(z,   p_zb, p_sumz,  NROWS);
    k_prep<<<1024, 256>>>(cbw, p_cb, p_cnorm, NC);
    dim3 grid(NROWS/128, NC/(TCH*128));   // x = row chunk (fastest)
    k_mma<<<grid, NTHR, SMEM_TOTAL>>>(p_zb, p_cb, p_cnorm, p_rmax, p_ccnt, p_cand);
    k_refine<<<4096, 256>>>(z, cbw, p_sumz, p_cnorm, p_ccnt, p_cand,
                            out_idx, out_zq, p_wsum, p_count, p_loss);
    k_ema<<<32, 256>>>(ema_count, p_count, out_cnt, p_n);
    k_codebook<<<8192, 256>>>(ema_weight, p_wsum, out_cnt, p_n, out_cb, out_ew);
    k_loss<<<1, 1>>>(p_loss, out_loss);
}

// round 16
// speedup vs baseline: 1.3518x; 1.0014x over previous
#include <cuda_runtime.h>
#include <cuda_bf16.h>
#include <cstdint>

#define NROWS 32768
#define DIM   256
#define NC    8192
#define HM    1e-4f             // score-space margin (= 2e-4 in dist space)
#define CAP   64
#define TCH   4                 // code chunks per CTA

#define NTHR  256               // 8 warps
#define PITCH 264               // bf16 elems/row smem pitch (256 + pad)
#define SM_A   0                // 128*264*2 = 67584
#define SM_B0  67584
#define SM_B1  135168
#define SMEM_TOTAL 202752       // A + 2 B stages

// ---------------- scratch ----------------------------------------------------
__device__ float g_sumz[NROWS];
__device__ float g_cnorm[NC];
__device__ float g_count[NC];
__device__ float g_wsum[NC * DIM];
__device__ float g_loss;
__device__ float g_n;
__device__ uint32_t g_rmax[NROWS];          // order-mapped score max per row
__device__ int      g_ccnt[NROWS];
__device__ int      g_cand[NROWS * CAP];
__device__ __nv_bfloat16 g_zb[NROWS * DIM];
__device__ __nv_bfloat16 g_cb[NC * DIM];

// ---------------- helpers -----------------------------------------------------
__device__ __forceinline__ uint32_t smem_u32(const void* p) {
    uint32_t a;
    asm("{ .reg .u64 t; cvta.to.shared.u64 t, %1; cvt.u32.u64 %0, t; }" : "=r"(a) : "l"(p));
    return a;
}
__device__ __forceinline__ void ldsm4(uint32_t& r0, uint32_t& r1, uint32_t& r2, uint32_t& r3, uint32_t addr) {
    asm volatile("ldmatrix.sync.aligned.m8n8.x4.shared.b16 {%0,%1,%2,%3}, [%4];"
                 : "=r"(r0), "=r"(r1), "=r"(r2), "=r"(r3) : "r"(addr));
}
__device__ __forceinline__ void mma16816(float* c, uint32_t a0, uint32_t a1, uint32_t a2, uint32_t a3,
                                         uint32_t b0, uint32_t b1) {
    asm volatile("mma.sync.aligned.m16n8k16.row.col.f32.bf16.bf16.f32 "
                 "{%0,%1,%2,%3}, {%4,%5,%6,%7}, {%8,%9}, {%0,%1,%2,%3};"
                 : "+f"(c[0]), "+f"(c[1]), "+f"(c[2]), "+f"(c[3])
                 : "r"(a0), "r"(a1), "r"(a2), "r"(a3), "r"(b0), "r"(b1));
}
__device__ __forceinline__ void cpasync16(uint32_t dst, const void* src) {
    asm volatile("cp.async.cg.shared.global [%0], [%1], 16;" :: "r"(dst), "l"(src));
}
// order-preserving float<->uint map (unsigned compare == float compare)
__device__ __forceinline__ uint32_t fmap(float f) {
    uint32_t b = __float_as_uint(f);
    return b ^ (uint32_t)(((int32_t)b >> 31) | 0x80000000);
}
__device__ __forceinline__ float funmap(uint32_t u) {
    uint32_t b = u ^ ((u >> 31) ? 0x80000000u : 0xFFFFFFFFu);
    return __uint_as_float(b);   // funmap(0) = NaN; fmaxf ignores NaN operand
}

// ---------------- zero scratch ------------------------------------------------
__global__ void k_zero() {
    int i = blockIdx.x * blockDim.x + threadIdx.x;
    int stride = gridDim.x * blockDim.x;
    for (int j = i; j < NC * DIM; j += stride) g_wsum[j] = 0.0f;
    for (int j = i; j < NROWS; j += stride) { g_rmax[j] = 0u; g_ccnt[j] = 0; }
    if (i < NC) g_count[i] = 0.0f;
    if (i == 0) { g_loss = 0.0f; g_n = 0.0f; }
}

// ---------------- prep: row norms + bf16 round --------------------------------
__global__ void k_prep(const float* __restrict__ x, __nv_bfloat16* __restrict__ ob,
                       float* __restrict__ norm, int rows) {
    int w = (blockIdx.x * blockDim.x + threadIdx.x) >> 5;
    int lane = threadIdx.x & 31;
    if (w >= rows) return;
    const float* row = x + (size_t)w * DIM;
    float s = 0.0f;
#pragma unroll
    for (int m = 0; m < 8; m++) { float v = row[lane + 32*m]; s = __fadd_rn(s, __fmul_rn(v, v)); }
#pragma unroll
    for (int o = 16; o > 0; o >>= 1) s = __fadd_rn(s, __shfl_down_sync(0xffffffffu, s, o));
    if (lane == 0) norm[w] = s;

    __align__(16) __nv_bfloat16 b0[8];
#pragma unroll
    for (int q = 0; q < 8; q++) b0[q] = __float2bfloat16_rn(row[lane*8 + q]);
    *reinterpret_cast<uint4*>(ob + (size_t)w*DIM + lane*8) = *reinterpret_cast<uint4*>(b0);
}

// ---------------- HMMA GEMM + global online candidate selection ----------------
// grid (256 row-chunks [x fastest], 16 code-quads). A resident; B double-buffered.
// Inner loop software-pipelines fragment LDSMs one k-step ahead of the MMAs.
__global__ void __launch_bounds__(NTHR, 1) k_mma(
    const __nv_bfloat16* __restrict__ zb, const __nv_bfloat16* __restrict__ cb,
    const float* __restrict__ cnorm,
    uint32_t* __restrict__ grmax, int* __restrict__ gccnt, int* __restrict__ gcand)
{
    extern __shared__ char smem[];
    __nv_bfloat16* As = reinterpret_cast<__nv_bfloat16*>(smem + SM_A);

    const int tid = threadIdx.x;
    const int row0 = blockIdx.x * 128;
    const int colbase = blockIdx.y * (TCH * 128);
    const uint32_t sbA = smem_u32(smem + SM_A);
    const uint32_t sbB[2] = { smem_u32(smem + SM_B0), smem_u32(smem + SM_B1) };

    // prefetch B0 (async), load A (sync) — overlap naturally
    {
        const __nv_bfloat16* Bg = cb + (size_t)colbase * DIM;
#pragma unroll
        for (int i = 0; i < 16; i++) {
            int u = tid + i * NTHR;
            int r = u >> 5, ch = u & 31;
            cpasync16(sbB[0] + (uint32_t)((r * PITCH + ch * 8) * 2), Bg + (size_t)r * DIM + ch * 8);
        }
        asm volatile("cp.async.commit_group;");
        const uint4* Ag = reinterpret_cast<const uint4*>(zb + (size_t)row0 * DIM);
#pragma unroll
        for (int i = 0; i < 16; i++) {
            int u = tid + i * NTHR;
            int r = u >> 5, ch = u & 31;
            reinterpret_cast<uint4*>(As + r * PITCH + ch * 8)[0] = Ag[u];
        }
    }

    const int wid = tid >> 5, lane = tid & 31;
    const int wm = wid & 3, wn = wid >> 2;          // 4 x 2 warp grid (32 x 64 tiles)
    const int gq = lane >> 2, t4 = lane & 3;
    const int rl0 = wm*32 + gq;

    const uint32_t aBase = sbA + (uint32_t)(((wm*32 + (lane & 15)) * PITCH + (lane >> 4) * 8) * 2);
    const uint32_t bOff  = (uint32_t)(((wn*64 + (lane & 15)) * PITCH + (lane >> 4) * 8) * 2);

    for (int t = 0; t < TCH; t++) {
        asm volatile("cp.async.wait_group 0;");
        __syncthreads();   // B(t) visible; all warps done with buffer (t+1)&1

        if (t + 1 < TCH) { // prefetch B(t+1) into the other buffer (hidden by compute)
            const __nv_bfloat16* Bg = cb + (size_t)(colbase + (t+1)*128) * DIM;
            uint32_t dbase = sbB[(t+1) & 1];
#pragma unroll
            for (int i = 0; i < 16; i++) {
                int u = tid + i * NTHR;
                int r = u >> 5, ch = u & 31;
                cpasync16(dbase + (uint32_t)((r * PITCH + ch * 8) * 2), Bg + (size_t)r * DIM + ch * 8);
            }
            asm volatile("cp.async.commit_group;");
        }

        const uint32_t bBase = sbB[t & 1] + bOff;
        const int col0 = colbase + t*128;

        float acc[2][8][4];
#pragma unroll
        for (int mt = 0; mt < 2; mt++)
#pragma unroll
            for (int nt = 0; nt < 8; nt++)
#pragma unroll
                for (int q = 0; q < 4; q++) acc[mt][nt][q] = 0.0f;

        // software-pipelined k-loop: fragments double-buffered, LDSM one step ahead
        uint32_t a[2][2][4], b[2][4][4];
#pragma unroll
        for (int mt = 0; mt < 2; mt++)
            ldsm4(a[0][mt][0], a[0][mt][1], a[0][mt][2], a[0][mt][3],
                  aBase + (uint32_t)(((mt*16)*PITCH) * 2));
#pragma unroll
        for (int ng = 0; ng < 4; ng++)
            ldsm4(b[0][ng][0], b[0][ng][1], b[0][ng][2], b[0][ng][3],
                  bBase + (uint32_t)(((ng*16)*PITCH) * 2));

#pragma unroll
        for (int k16 = 0; k16 < 16; k16++) {
            const int cur = k16 & 1, nxt = cur ^ 1;
            if (k16 < 15) {
#pragma unroll
                for (int mt = 0; mt < 2; mt++)
                    ldsm4(a[nxt][mt][0], a[nxt][mt][1], a[nxt][mt][2], a[nxt][mt][3],
                          aBase + (uint32_t)(((mt*16)*PITCH + (k16+1)*16) * 2));
#pragma unroll
                for (int ng = 0; ng < 4; ng++)
                    ldsm4(b[nxt][ng][0], b[nxt][ng][1], b[nxt][ng][2], b[nxt][ng][3],
                          bBase + (uint32_t)(((ng*16)*PITCH + (k16+1)*16) * 2));
            }
#pragma unroll
            for (int mt = 0; mt < 2; mt++)
#pragma unroll
                for (int ng = 0; ng < 4; ng++) {
                    mma16816(acc[mt][2*ng+0], a[cur][mt][0], a[cur][mt][1], a[cur][mt][2], a[cur][mt][3],
                             b[cur][ng][0], b[cur][ng][2]);
                    mma16816(acc[mt][2*ng+1], a[cur][mt][0], a[cur][mt][1], a[cur][mt][2], a[cur][mt][3],
                             b[cur][ng][1], b[cur][ng][3]);
                }
        }

        // ---- score-space epilogue with GLOBAL running max ------------------
#pragma unroll
        for (int mt = 0; mt < 2; mt++) {
            float sc[8][4];
            float mx_lo = -3.4e38f, mx_hi = -3.4e38f;
#pragma unroll
            for (int nt = 0; nt < 8; nt++) {
                int col = col0 + wn*64 + nt*8 + t4*2;
                float2 cn = *reinterpret_cast<const float2*>(cnorm + col);
                sc[nt][0] = __fmaf_rn(cn.x, -0.5f, acc[mt][nt][0]);
                sc[nt][1] = __fmaf_rn(cn.y, -0.5f, acc[mt][nt][1]);
                sc[nt][2] = __fmaf_rn(cn.x, -0.5f, acc[mt][nt][2]);
                sc[nt][3] = __fmaf_rn(cn.y, -0.5f, acc[mt][nt][3]);
                mx_lo = fmaxf(mx_lo, fmaxf(sc[nt][0], sc[nt][1]));
                mx_hi = fmaxf(mx_hi, fmaxf(sc[nt][2], sc[nt][3]));
            }
#pragma unroll
            for (int o = 1; o < 4; o <<= 1) {
                mx_lo = fmaxf(mx_lo, __shfl_xor_sync(0xffffffffu, mx_lo, o));
                mx_hi = fmaxf(mx_hi, __shfl_xor_sync(0xffffffffu, mx_hi, o));
            }
            int rlo = row0 + rl0 + mt*16, rhi = rlo + 8;
            uint32_t old_lo = 0u, old_hi = 0u;
            if (t4 == 0) {
                old_lo = atomicMax(&grmax[rlo], fmap(mx_lo));
                old_hi = atomicMax(&grmax[rhi], fmap(mx_hi));
            }
            old_lo = __shfl_sync(0xffffffffu, old_lo, lane & ~3);
            old_hi = __shfl_sync(0xffffffffu, old_hi, lane & ~3);
            float Tlo = fmaxf(mx_lo, funmap(old_lo)) - HM;
            float Thi = fmaxf(mx_hi, funmap(old_hi)) - HM;
#pragma unroll
            for (int nt = 0; nt < 8; nt++) {
                int col = col0 + wn*64 + nt*8 + t4*2;
#pragma unroll
                for (int q = 0; q < 4; q++) {
                    int r    = (q < 2) ? rlo : rhi;
                    float T  = (q < 2) ? Tlo : Thi;
                    if (sc[nt][q] >= T) {
                        int pos = atomicAdd(&gccnt[r], 1);
                        if (pos < CAP) gcand[r*CAP + pos] = col + (q & 1);
                    }
                }
            }
        }
    }
}

// ---------------- warp-cooperative exact refinement + scatter ------------------
__global__ void k_refine(const float* __restrict__ zf, const float* __restrict__ cbw,
                         const float* __restrict__ sumz, const float* __restrict__ cnorm,
                         const int* __restrict__ gccnt, const int* __restrict__ gcand,
                         float* __restrict__ idxf_out, float* __restrict__ zq_out,
                         float* __restrict__ wsum, float* __restrict__ cnt,
                         float* __restrict__ lossacc) {
    int w = (blockIdx.x * blockDim.x + threadIdx.x) >> 5;
    int lane = threadIdx.x & 31;
    if (w >= NROWS) return;
    const float* zr = zf + (size_t)w * DIM;
    float szr = sumz[w];

    float zv[8];
#pragma unroll
    for (int m = 0; m < 8; m++) zv[m] = zr[lane + 32*m];

    float bv = 3.4e38f; int bi = NC;
    int n = gccnt[w];
    if (n <= CAP) {
        for (int i = 0; i < n; i++) {
            int cc = gcand[w*CAP + i];                   // broadcast load
            const float* cr = cbw + (size_t)cc * DIM;
            float s = 0.0f;
#pragma unroll
            for (int m = 0; m < 8; m++) s = __fmaf_rn(zv[m], cr[lane + 32*m], s);
#pragma unroll
            for (int o = 16; o > 0; o >>= 1) s = __fadd_rn(s, __shfl_xor_sync(0xffffffffu, s, o));
            float de = __fadd_rn(__fadd_rn(szr, -2.0f * s), cnorm[cc]);
            if (de < bv || (de == bv && cc < bi)) { bv = de; bi = cc; }
        }
    } else {
        for (int cc = lane; cc < NC; cc += 32) {
            const float* cr = cbw + (size_t)cc * DIM;
            float acc2 = 0.0f;
            for (int k2 = 0; k2 < DIM; k2++) acc2 = __fmaf_rn(zr[k2], cr[k2], acc2);
            float de = __fadd_rn(__fadd_rn(szr, -2.0f * acc2), cnorm[cc]);
            if (de < bv || (de == bv && cc < bi)) { bv = de; bi = cc; }
        }
#pragma unroll
        for (int o = 16; o > 0; o >>= 1) {
            float ov = __shfl_xor_sync(0xffffffffu, bv, o);
            int   oi = __shfl_xor_sync(0xffffffffu, bi, o);
            if (ov < bv || (ov == bv && oi < bi)) { bv = ov; bi = oi; }
        }
    }
    if (lane == 0) idxf_out[w] = (float)bi;

    const float* cr = cbw + (size_t)bi * DIM;
    float ls = 0.0f;
#pragma unroll
    for (int m = 0; m < 8; m++) {
        int d = lane + 32*m;
        float zvv = zv[m], cv = cr[d];
        atomicAdd(&wsum[bi * DIM + d], zvv);
        float diff = __fadd_rn(zvv, -cv);
        ls = __fadd_rn(ls, __fmul_rn(diff, diff));
        float st = __fadd_rn(cv, -zvv);
        zq_out[(size_t)w * DIM + d] = __fadd_rn(zvv, st);
    }
#pragma unroll
    for (int o = 16; o > 0; o >>= 1) ls = __fadd_rn(ls, __shfl_down_sync(0xffffffffu, ls, o));
    if (lane == 0) { atomicAdd(&cnt[bi], 1.0f); atomicAdd(lossacc, ls); }
}

// ---------------- EMA count + n ----------------------------------------------
__global__ void k_ema(const float* __restrict__ ema_count, const float* __restrict__ cntv,
                      float* __restrict__ out_count, float* __restrict__ n_acc) {
    int c = blockIdx.x * blockDim.x + threadIdx.x;
    float nec = 0.0f;
    if (c < NC) {
        nec = __fadd_rn(__fmul_rn(0.99f, ema_count[c]), __fmul_rn(0.01f, cntv[c]));
        out_count[c] = nec;
    }
    __shared__ float red[256];
    red[threadIdx.x] = nec;
    __syncthreads();
    for (int s = 128; s > 0; s >>= 1) {
        if (threadIdx.x < s) red[threadIdx.x] = __fadd_rn(red[threadIdx.x], red[threadIdx.x + s]);
        __syncthreads();
    }
    if (threadIdx.x == 0) atomicAdd(n_acc, red[0]);
}

// ---------------- new codebook + new ema weight -------------------------------
__global__ void k_codebook(const float* __restrict__ ema_weight, const float* __restrict__ wsum,
                           const float* __restrict__ out_count, const float* __restrict__ n_acc,
                           float* __restrict__ out_cb, float* __restrict__ out_ew) {
    size_t i = (size_t)blockIdx.x * 256 + threadIdx.x;
    if (i >= (size_t)NC * DIM) return;
    int c = (int)(i >> 8);
    float new_ew = __fadd_rn(__fmul_rn(0.99f, ema_weight[i]), __fmul_rn(0.01f, wsum[i]));
    out_ew[i] = new_ew;
    float n  = *n_acc;
    float a  = __fadd_rn(out_count[c], 1e-5f);
    float b  = __fadd_rn(n, 0.08192f);
    float cs = __fmul_rn(__fdiv_rn(a, b), n);
    out_cb[i] = __fdiv_rn(new_ew, cs);
}

__global__ void k_loss(const float* __restrict__ lossacc, float* __restrict__ out_loss) {
    float m = __fdiv_rn(*lossacc, 8388608.0f);
    *out_loss = __fmul_rn(0.25f, m);
}

// ---------------- launch ------------------------------------------------------
extern "C" void kernel_launch(void* const* d_in, const int* in_sizes, int n_in,
                              void* d_out, int out_size) {
    const float* z          = (const float*)d_in[0];
    const float* cbw        = (const float*)d_in[1];
    const float* ema_count  = (const float*)d_in[2];
    const float* ema_weight = (const float*)d_in[3];

    float* out      = (float*)d_out;
    float* out_zq   = out;
    float* out_idx  = out + 8388608;
    float* out_loss = out + 8421376;
    float* out_cb   = out + 8421377;
    float* out_cnt  = out + 10518529;
    float* out_ew   = out + 10526721;

    float *p_sumz, *p_cnorm, *p_count, *p_wsum, *p_loss, *p_n;
    uint32_t* p_rmax;
    int *p_ccnt, *p_cand;
    __nv_bfloat16 *p_zb, *p_cb;
    cudaGetSymbolAddress((void**)&p_sumz,  g_sumz);
    cudaGetSymbolAddress((void**)&p_cnorm, g_cnorm);
    cudaGetSymbolAddress((void**)&p_count, g_count);
    cudaGetSymbolAddress((void**)&p_wsum,  g_wsum);
    cudaGetSymbolAddress((void**)&p_loss,  g_loss);
    cudaGetSymbolAddress((void**)&p_n,     g_n);
    cudaGetSymbolAddress((void**)&p_rmax,  g_rmax);
    cudaGetSymbolAddress((void**)&p_ccnt,  g_ccnt);
    cudaGetSymbolAddress((void**)&p_cand,  g_cand);
    cudaGetSymbolAddress((void**)&p_zb,    g_zb);
    cudaGetSymbolAddress((void**)&p_cb,    g_cb);

    cudaFuncSetAttribute(k_mma, cudaFuncAttributeMaxDynamicSharedMemorySize, SMEM_TOTAL);

    k_zero<<<2048, 256>>>();
    k_prep<<<4096, 256>>>(z,   p_zb, p_sumz,  NROWS);
    k_prep<<<1024, 256>>>(cbw, p_cb, p_cnorm, NC);
    dim3 grid(NROWS/128, NC/(TCH*128));   // x = row chunk (fastest)
    k_mma<<<grid, NTHR, SMEM_TOTAL>>>(p_zb, p_cb, p_cnorm, p_rmax, p_ccnt, p_cand);
    k_refine<<<4096, 256>>>(z, cbw, p_sumz, p_cnorm, p_ccnt, p_cand,
                            out_idx, out_zq, p_wsum, p_count, p_loss);
    k_ema<<<32, 256>>>(ema_count, p_count, out_cnt, p_n);
    k_codebook<<<8192, 256>>>(ema_weight, p_wsum, out_cnt, p_n, out_cb, out_ew);
    k_loss<<<1, 1>>>(p_loss, out_loss);
}

// round 17
// speedup vs baseline: 1.3781x; 1.0195x over previous
#include <cuda_runtime.h>
#include <cuda_bf16.h>
#include <cstdint>

#define NROWS 32768
#define DIM   256
#define NC    8192
#define HM    1e-4f             // score-space margin (= 2e-4 in dist space)
#define CAP   64
#define TCH   8                 // code chunks per CTA

#define NTHR  256               // 8 warps
#define PITCH 264               // bf16 elems/row smem pitch (256 + pad)
#define SM_A   0                // 128*264*2 = 67584
#define SM_B0  67584
#define SM_B1  135168
#define SMEM_TOTAL 202752       // A + 2 B stages

// ---------------- scratch ----------------------------------------------------
__device__ float g_sumz[NROWS];
__device__ float g_cnorm[NC];
__device__ float g_count[NC];
__device__ float g_wsum[NC * DIM];
__device__ float g_loss;
__device__ float g_n;
__device__ uint32_t g_rmax[NROWS];          // order-mapped score max per row
__device__ int      g_ccnt[NROWS];
__device__ int      g_cand[NROWS * CAP];
__device__ __nv_bfloat16 g_zb[NROWS * DIM];
__device__ __nv_bfloat16 g_cb[NC * DIM];

// ---------------- helpers -----------------------------------------------------
__device__ __forceinline__ uint32_t smem_u32(const void* p) {
    uint32_t a;
    asm("{ .reg .u64 t; cvta.to.shared.u64 t, %1; cvt.u32.u64 %0, t; }" : "=r"(a) : "l"(p));
    return a;
}
__device__ __forceinline__ void ldsm4(uint32_t& r0, uint32_t& r1, uint32_t& r2, uint32_t& r3, uint32_t addr) {
    asm volatile("ldmatrix.sync.aligned.m8n8.x4.shared.b16 {%0,%1,%2,%3}, [%4];"
                 : "=r"(r0), "=r"(r1), "=r"(r2), "=r"(r3) : "r"(addr));
}
__device__ __forceinline__ void mma16816(float* c, uint32_t a0, uint32_t a1, uint32_t a2, uint32_t a3,
                                         uint32_t b0, uint32_t b1) {
    asm volatile("mma.sync.aligned.m16n8k16.row.col.f32.bf16.bf16.f32 "
                 "{%0,%1,%2,%3}, {%4,%5,%6,%7}, {%8,%9}, {%0,%1,%2,%3};"
                 : "+f"(c[0]), "+f"(c[1]), "+f"(c[2]), "+f"(c[3])
                 : "r"(a0), "r"(a1), "r"(a2), "r"(a3), "r"(b0), "r"(b1));
}
__device__ __forceinline__ void cpasync16(uint32_t dst, const void* src) {
    asm volatile("cp.async.cg.shared.global [%0], [%1], 16;" :: "r"(dst), "l"(src));
}
// order-preserving float<->uint map (unsigned compare == float compare)
__device__ __forceinline__ uint32_t fmap(float f) {
    uint32_t b = __float_as_uint(f);
    return b ^ (uint32_t)(((int32_t)b >> 31) | 0x80000000);
}
__device__ __forceinline__ float funmap(uint32_t u) {
    uint32_t b = u ^ ((u >> 31) ? 0x80000000u : 0xFFFFFFFFu);
    return __uint_as_float(b);   // funmap(0) = NaN; fmaxf ignores NaN operand
}

// ---------------- prep z: row norms + bf16 round + zero rmax/ccnt --------------
__global__ void k_prep_z(const float* __restrict__ x, __nv_bfloat16* __restrict__ ob,
                         float* __restrict__ norm,
                         uint32_t* __restrict__ rmax, int* __restrict__ ccnt) {
    int w = (blockIdx.x * blockDim.x + threadIdx.x) >> 5;
    int lane = threadIdx.x & 31;
    if (w >= NROWS) return;
    const float* row = x + (size_t)w * DIM;
    float s = 0.0f;
#pragma unroll
    for (int m = 0; m < 8; m++) { float v = row[lane + 32*m]; s = __fadd_rn(s, __fmul_rn(v, v)); }
#pragma unroll
    for (int o = 16; o > 0; o >>= 1) s = __fadd_rn(s, __shfl_down_sync(0xffffffffu, s, o));
    if (lane == 0) { norm[w] = s; rmax[w] = 0u; ccnt[w] = 0; }

    __align__(16) __nv_bfloat16 b0[8];
#pragma unroll
    for (int q = 0; q < 8; q++) b0[q] = __float2bfloat16_rn(row[lane*8 + q]);
    *reinterpret_cast<uint4*>(ob + (size_t)w*DIM + lane*8) = *reinterpret_cast<uint4*>(b0);
}

// ---------------- prep cb: norms + bf16 + zero wsum/count/loss/n ---------------
__global__ void k_prep_cb(const float* __restrict__ x, __nv_bfloat16* __restrict__ ob,
                          float* __restrict__ norm,
                          float* __restrict__ wsum, float* __restrict__ cnt,
                          float* __restrict__ lossacc, float* __restrict__ n_acc) {
    int w = (blockIdx.x * blockDim.x + threadIdx.x) >> 5;
    int lane = threadIdx.x & 31;
    if (w >= NC) return;
    const float* row = x + (size_t)w * DIM;
    float s = 0.0f;
#pragma unroll
    for (int m = 0; m < 8; m++) { float v = row[lane + 32*m]; s = __fadd_rn(s, __fmul_rn(v, v)); }
#pragma unroll
    for (int o = 16; o > 0; o >>= 1) s = __fadd_rn(s, __shfl_down_sync(0xffffffffu, s, o));
    if (lane == 0) { norm[w] = s; cnt[w] = 0.0f; }
    if (w == 0 && lane == 0) { *lossacc = 0.0f; *n_acc = 0.0f; }

    // zero wsum row (coalesced float4)
    float4 z4 = make_float4(0.f, 0.f, 0.f, 0.f);
#pragma unroll
    for (int m = 0; m < 2; m++)
        *reinterpret_cast<float4*>(wsum + (size_t)w*DIM + (lane + 32*m)*4) = z4;

    __align__(16) __nv_bfloat16 b0[8];
#pragma unroll
    for (int q = 0; q < 8; q++) b0[q] = __float2bfloat16_rn(row[lane*8 + q]);
    *reinterpret_cast<uint4*>(ob + (size_t)w*DIM + lane*8) = *reinterpret_cast<uint4*>(b0);
}

// ---------------- HMMA GEMM + global online candidate selection ----------------
// grid (256 row-chunks [x fastest], 8 code-octets). A resident; B double-buffered.
__global__ void __launch_bounds__(NTHR, 1) k_mma(
    const __nv_bfloat16* __restrict__ zb, const __nv_bfloat16* __restrict__ cb,
    const float* __restrict__ cnorm,
    uint32_t* __restrict__ grmax, int* __restrict__ gccnt, int* __restrict__ gcand)
{
    extern __shared__ char smem[];
    __nv_bfloat16* As = reinterpret_cast<__nv_bfloat16*>(smem + SM_A);

    const int tid = threadIdx.x;
    const int row0 = blockIdx.x * 128;
    const int colbase = blockIdx.y * (TCH * 128);
    const uint32_t sbA = smem_u32(smem + SM_A);
    const uint32_t sbB[2] = { smem_u32(smem + SM_B0), smem_u32(smem + SM_B1) };

    // prefetch B0 (async), load A (sync) — overlap naturally
    {
        const __nv_bfloat16* Bg = cb + (size_t)colbase * DIM;
#pragma unroll
        for (int i = 0; i < 16; i++) {
            int u = tid + i * NTHR;
            int r = u >> 5, ch = u & 31;
            cpasync16(sbB[0] + (uint32_t)((r * PITCH + ch * 8) * 2), Bg + (size_t)r * DIM + ch * 8);
        }
        asm volatile("cp.async.commit_group;");
        const uint4* Ag = reinterpret_cast<const uint4*>(zb + (size_t)row0 * DIM);
#pragma unroll
        for (int i = 0; i < 16; i++) {
            int u = tid + i * NTHR;
            int r = u >> 5, ch = u & 31;
            reinterpret_cast<uint4*>(As + r * PITCH + ch * 8)[0] = Ag[u];
        }
    }

    const int wid = tid >> 5, lane = tid & 31;
    const int wm = wid & 3, wn = wid >> 2;          // 4 x 2 warp grid (32 x 64 tiles)
    const int gq = lane >> 2, t4 = lane & 3;
    const int rl0 = wm*32 + gq;

    const uint32_t aBase = sbA + (uint32_t)(((wm*32 + (lane & 15)) * PITCH + (lane >> 4) * 8) * 2);
    const uint32_t bOff  = (uint32_t)(((wn*64 + (lane & 15)) * PITCH + (lane >> 4) * 8) * 2);

    for (int t = 0; t < TCH; t++) {
        asm volatile("cp.async.wait_group 0;");
        __syncthreads();   // B(t) visible; all warps done with buffer (t+1)&1

        if (t + 1 < TCH) { // prefetch B(t+1) into the other buffer (hidden by compute)
            const __nv_bfloat16* Bg = cb + (size_t)(colbase + (t+1)*128) * DIM;
            uint32_t dbase = sbB[(t+1) & 1];
#pragma unroll
            for (int i = 0; i < 16; i++) {
                int u = tid + i * NTHR;
                int r = u >> 5, ch = u & 31;
                cpasync16(dbase + (uint32_t)((r * PITCH + ch * 8) * 2), Bg + (size_t)r * DIM + ch * 8);
            }
            asm volatile("cp.async.commit_group;");
        }

        const uint32_t bBase = sbB[t & 1] + bOff;
        const int col0 = colbase + t*128;

        float acc[2][8][4];
#pragma unroll
        for (int mt = 0; mt < 2; mt++)
#pragma unroll
            for (int nt = 0; nt < 8; nt++)
#pragma unroll
                for (int q = 0; q < 4; q++) acc[mt][nt][q] = 0.0f;

        // 16 uninterrupted k-steps: 96 LDSM + 256 MMA per warp
#pragma unroll
        for (int k16 = 0; k16 < 16; k16++) {
            uint32_t a[2][4], b[4][4];
#pragma unroll
            for (int mt = 0; mt < 2; mt++)
                ldsm4(a[mt][0], a[mt][1], a[mt][2], a[mt][3],
                      aBase + (uint32_t)(((mt*16)*PITCH + k16*16) * 2));
#pragma unroll
            for (int ng = 0; ng < 4; ng++)
                ldsm4(b[ng][0], b[ng][1], b[ng][2], b[ng][3],
                      bBase + (uint32_t)(((ng*16)*PITCH + k16*16) * 2));
#pragma unroll
            for (int mt = 0; mt < 2; mt++)
#pragma unroll
                for (int ng = 0; ng < 4; ng++) {
                    mma16816(acc[mt][2*ng+0], a[mt][0], a[mt][1], a[mt][2], a[mt][3], b[ng][0], b[ng][2]);
                    mma16816(acc[mt][2*ng+1], a[mt][0], a[mt][1], a[mt][2], a[mt][3], b[ng][1], b[ng][3]);
                }
        }

        // ---- score-space epilogue with GLOBAL running max ------------------
#pragma unroll
        for (int mt = 0; mt < 2; mt++) {
            float sc[8][4];
            float mx_lo = -3.4e38f, mx_hi = -3.4e38f;
#pragma unroll
            for (int nt = 0; nt < 8; nt++) {
                int col = col0 + wn*64 + nt*8 + t4*2;
                float2 cn = *reinterpret_cast<const float2*>(cnorm + col);
                sc[nt][0] = __fmaf_rn(cn.x, -0.5f, acc[mt][nt][0]);
                sc[nt][1] = __fmaf_rn(cn.y, -0.5f, acc[mt][nt][1]);
                sc[nt][2] = __fmaf_rn(cn.x, -0.5f, acc[mt][nt][2]);
                sc[nt][3] = __fmaf_rn(cn.y, -0.5f, acc[mt][nt][3]);
                mx_lo = fmaxf(mx_lo, fmaxf(sc[nt][0], sc[nt][1]));
                mx_hi = fmaxf(mx_hi, fmaxf(sc[nt][2], sc[nt][3]));
            }
#pragma unroll
            for (int o = 1; o < 4; o <<= 1) {
                mx_lo = fmaxf(mx_lo, __shfl_xor_sync(0xffffffffu, mx_lo, o));
                mx_hi = fmaxf(mx_hi, __shfl_xor_sync(0xffffffffu, mx_hi, o));
            }
            int rlo = row0 + rl0 + mt*16, rhi = rlo + 8;
            uint32_t old_lo = 0u, old_hi = 0u;
            if (t4 == 0) {
                old_lo = atomicMax(&grmax[rlo], fmap(mx_lo));
                old_hi = atomicMax(&grmax[rhi], fmap(mx_hi));
            }
            old_lo = __shfl_sync(0xffffffffu, old_lo, lane & ~3);
            old_hi = __shfl_sync(0xffffffffu, old_hi, lane & ~3);
            float Tlo = fmaxf(mx_lo, funmap(old_lo)) - HM;
            float Thi = fmaxf(mx_hi, funmap(old_hi)) - HM;
#pragma unroll
            for (int nt = 0; nt < 8; nt++) {
                int col = col0 + wn*64 + nt*8 + t4*2;
#pragma unroll
                for (int q = 0; q < 4; q++) {
                    int r    = (q < 2) ? rlo : rhi;
                    float T  = (q < 2) ? Tlo : Thi;
                    if (sc[nt][q] >= T) {
                        int pos = atomicAdd(&gccnt[r], 1);
                        if (pos < CAP) gcand[r*CAP + pos] = col + (q & 1);
                    }
                }
            }
        }
    }
}

// ---------------- warp-cooperative exact refinement + scatter ------------------
__global__ void k_refine(const float* __restrict__ zf, const float* __restrict__ cbw,
                         const float* __restrict__ sumz, const float* __restrict__ cnorm,
                         const int* __restrict__ gccnt, const int* __restrict__ gcand,
                         float* __restrict__ idxf_out, float* __restrict__ zq_out,
                         float* __restrict__ wsum, float* __restrict__ cnt,
                         float* __restrict__ lossacc) {
    int w = (blockIdx.x * blockDim.x + threadIdx.x) >> 5;
    int lane = threadIdx.x & 31;
    if (w >= NROWS) return;
    const float* zr = zf + (size_t)w * DIM;
    float szr = sumz[w];

    float zv[8];
#pragma unroll
    for (int m = 0; m < 8; m++) zv[m] = zr[lane + 32*m];

    float bv = 3.4e38f; int bi = NC;
    int n = gccnt[w];
    if (n <= CAP) {
        for (int i = 0; i < n; i++) {
            int cc = gcand[w*CAP + i];                   // broadcast load
            const float* cr = cbw + (size_t)cc * DIM;
            float s = 0.0f;
#pragma unroll
            for (int m = 0; m < 8; m++) s = __fmaf_rn(zv[m], cr[lane + 32*m], s);
#pragma unroll
            for (int o = 16; o > 0; o >>= 1) s = __fadd_rn(s, __shfl_xor_sync(0xffffffffu, s, o));
            float de = __fadd_rn(__fadd_rn(szr, -2.0f * s), cnorm[cc]);
            if (de < bv || (de == bv && cc < bi)) { bv = de; bi = cc; }
        }
    } else {
        for (int cc = lane; cc < NC; cc += 32) {
            const float* cr = cbw + (size_t)cc * DIM;
            float acc2 = 0.0f;
            for (int k2 = 0; k2 < DIM; k2++) acc2 = __fmaf_rn(zr[k2], cr[k2], acc2);
            float de = __fadd_rn(__fadd_rn(szr, -2.0f * acc2), cnorm[cc]);
            if (de < bv || (de == bv && cc < bi)) { bv = de; bi = cc; }
        }
#pragma unroll
        for (int o = 16; o > 0; o >>= 1) {
            float ov = __shfl_xor_sync(0xffffffffu, bv, o);
            int   oi = __shfl_xor_sync(0xffffffffu, bi, o);
            if (ov < bv || (ov == bv && oi < bi)) { bv = ov; bi = oi; }
        }
    }
    if (lane == 0) idxf_out[w] = (float)bi;

    const float* cr = cbw + (size_t)bi * DIM;
    float ls = 0.0f;
#pragma unroll
    for (int m = 0; m < 8; m++) {
        int d = lane + 32*m;
        float zvv = zv[m], cv = cr[d];
        atomicAdd(&wsum[bi * DIM + d], zvv);
        float diff = __fadd_rn(zvv, -cv);
        ls = __fadd_rn(ls, __fmul_rn(diff, diff));
        float st = __fadd_rn(cv, -zvv);
        zq_out[(size_t)w * DIM + d] = __fadd_rn(zvv, st);
    }
#pragma unroll
    for (int o = 16; o > 0; o >>= 1) ls = __fadd_rn(ls, __shfl_down_sync(0xffffffffu, ls, o));
    if (lane == 0) { atomicAdd(&cnt[bi], 1.0f); atomicAdd(lossacc, ls); }
}

// ---------------- EMA count + n + loss finalize --------------------------------
__global__ void k_ema(const float* __restrict__ ema_count, const float* __restrict__ cntv,
                      float* __restrict__ out_count, float* __restrict__ n_acc,
                      const float* __restrict__ lossacc, float* __restrict__ out_loss) {
    int c = blockIdx.x * blockDim.x + threadIdx.x;
    float nec = 0.0f;
    if (c < NC) {
        nec = __fadd_rn(__fmul_rn(0.99f, ema_count[c]), __fmul_rn(0.01f, cntv[c]));
        out_count[c] = nec;
    }
    if (c == 0) {
        float m = __fdiv_rn(*lossacc, 8388608.0f);
        *out_loss = __fmul_rn(0.25f, m);
    }
    __shared__ float red[256];
    red[threadIdx.x] = nec;
    __syncthreads();
    for (int s = 128; s > 0; s >>= 1) {
        if (threadIdx.x < s) red[threadIdx.x] = __fadd_rn(red[threadIdx.x], red[threadIdx.x + s]);
        __syncthreads();
    }
    if (threadIdx.x == 0) atomicAdd(n_acc, red[0]);
}

// ---------------- new codebook + new ema weight -------------------------------
__global__ void k_codebook(const float* __restrict__ ema_weight, const float* __restrict__ wsum,
                           const float* __restrict__ out_count, const float* __restrict__ n_acc,
                           float* __restrict__ out_cb, float* __restrict__ out_ew) {
    size_t i = (size_t)blockIdx.x * 256 + threadIdx.x;
    if (i >= (size_t)NC * DIM) return;
    int c = (int)(i >> 8);
    float new_ew = __fadd_rn(__fmul_rn(0.99f, ema_weight[i]), __fmul_rn(0.01f, wsum[i]));
    out_ew[i] = new_ew;
    float n  = *n_acc;
    float a  = __fadd_rn(out_count[c], 1e-5f);
    float b  = __fadd_rn(n, 0.08192f);
    float cs = __fmul_rn(__fdiv_rn(a, b), n);
    out_cb[i] = __fdiv_rn(new_ew, cs);
}

// ---------------- launch ------------------------------------------------------
extern "C" void kernel_launch(void* const* d_in, const int* in_sizes, int n_in,
                              void* d_out, int out_size) {
    const float* z          = (const float*)d_in[0];
    const float* cbw        = (const float*)d_in[1];
    const float* ema_count  = (const float*)d_in[2];
    const float* ema_weight = (const float*)d_in[3];

    float* out      = (float*)d_out;
    float* out_zq   = out;
    float* out_idx  = out + 8388608;
    float* out_loss = out + 8421376;
    float* out_cb   = out + 8421377;
    float* out_cnt  = out + 10518529;
    float* out_ew   = out + 10526721;

    float *p_sumz, *p_cnorm, *p_count, *p_wsum, *p_loss, *p_n;
    uint32_t* p_rmax;
    int *p_ccnt, *p_cand;
    __nv_bfloat16 *p_zb, *p_cb;
    cudaGetSymbolAddress((void**)&p_sumz,  g_sumz);
    cudaGetSymbolAddress((void**)&p_cnorm, g_cnorm);
    cudaGetSymbolAddress((void**)&p_count, g_count);
    cudaGetSymbolAddress((void**)&p_wsum,  g_wsum);
    cudaGetSymbolAddress((void**)&p_loss,  g_loss);
    cudaGetSymbolAddress((void**)&p_n,     g_n);
    cudaGetSymbolAddress((void**)&p_rmax,  g_rmax);
    cudaGetSymbolAddress((void**)&p_ccnt,  g_ccnt);
    cudaGetSymbolAddress((void**)&p_cand,  g_cand);
    cudaGetSymbolAddress((void**)&p_zb,    g_zb);
    cudaGetSymbolAddress((void**)&p_cb,    g_cb);

    cudaFuncSetAttribute(k_mma, cudaFuncAttributeMaxDynamicSharedMemorySize, SMEM_TOTAL);

    k_prep_z<<<4096, 256>>>(z, p_zb, p_sumz, p_rmax, p_ccnt);
    k_prep_cb<<<1024, 256>>>(cbw, p_cb, p_cnorm, p_wsum, p_count, p_loss, p_n);
    dim3 grid(NROWS/128, NC/(TCH*128));   // x = row chunk (fastest)
    k_mma<<<grid, NTHR, SMEM_TOTAL>>>(p_zb, p_cb, p_cnorm, p_rmax, p_ccnt, p_cand);
    k_refine<<<4096, 256>>>(z, cbw, p_sumz, p_cnorm, p_ccnt, p_cand,
                            out_idx, out_zq, p_wsum, p_count, p_loss);
    k_ema<<<32, 256>>>(ema_count, p_count, out_cnt, p_n, p_loss, out_loss);
    k_codebook<<<8192, 256>>>(ema_weight, p_wsum, out_cnt, p_n, out_cb, out_ew);
}